// round 2
// baseline (speedup 1.0000x reference)
#include <cuda_runtime.h>
#include <math.h>

typedef unsigned long long ull;

#define NN 4096
#define NE 8192
#define NG 256
#define OUTC 256

// ---------------- static device scratch (no runtime allocation) ----------------
__device__ float g_P[(size_t)NN * 8704];   // P matrix (reused by both conv layers), 142.6 MB
__device__ float g_h[NN * OUTC];           // conv1 output (relu'd)
__device__ float g_h2[NN * OUTC];          // conv2 output
__device__ int   g_deg[NN];
__device__ int   g_off[NN + 1];
__device__ int   g_rank[NE];
__device__ int   g_csr[NE];
__device__ int   g_starts[NG + 1];

// ---------------- f32x2 helpers (sm_103a packed fp32 FFMA2) ----------------
__device__ __forceinline__ ull ffma2(ull a, ull b, ull c) {
    ull d; asm("fma.rn.f32x2 %0, %1, %2, %3;" : "=l"(d) : "l"(a), "l"(b), "l"(c)); return d;
}
__device__ __forceinline__ ull dup2(float v) {
    ull d; unsigned u = __float_as_uint(v);
    asm("mov.b64 %0, {%1, %1};" : "=l"(d) : "r"(u)); return d;
}
__device__ __forceinline__ void unpk(ull v, float &lo, float &hi) {
    asm("mov.b64 {%0, %1}, %2;" : "=f"(lo), "=f"(hi) : "l"(v));
}

// ---------------- deterministic CSR build ----------------
__global__ __launch_bounds__(256) void zero_deg_kernel() {
    int i = blockIdx.x * 256 + threadIdx.x;
    if (i < NN) g_deg[i] = 0;
}

// rank[e] = #earlier edges with same dst (stable order); also degree counts
__global__ __launch_bounds__(256) void rank_kernel(const int* __restrict__ dstA) {
    __shared__ int sd[NE];   // 32 KB
    const int t = threadIdx.x;
    for (int i = t; i < NE; i += 256) sd[i] = dstA[i];
    __syncthreads();
    const int e = blockIdx.x * 256 + t;
    const int de = sd[e];
    int r = 0;
    for (int j = 0; j < e; j++) r += (sd[j] == de) ? 1 : 0;
    g_rank[e] = r;
    atomicAdd(&g_deg[de], 1);
}

__global__ __launch_bounds__(1024) void scan_kernel() {
    __shared__ int s[1024];
    const int t = threadIdx.x;
    int l0 = g_deg[4 * t + 0], l1 = g_deg[4 * t + 1];
    int l2 = g_deg[4 * t + 2], l3 = g_deg[4 * t + 3];
    int tot = l0 + l1 + l2 + l3;
    s[t] = tot;
    __syncthreads();
    for (int off = 1; off < 1024; off <<= 1) {
        int v = (t >= off) ? s[t - off] : 0;
        __syncthreads();
        s[t] += v;
        __syncthreads();
    }
    int excl = s[t] - tot;
    g_off[4 * t + 0] = excl;
    g_off[4 * t + 1] = excl + l0;
    g_off[4 * t + 2] = excl + l0 + l1;
    g_off[4 * t + 3] = excl + l0 + l1 + l2;
    if (t == 1023) g_off[NN] = excl + tot;
}

__global__ __launch_bounds__(256) void place_kernel(const int* __restrict__ dstA) {
    const int e = blockIdx.x * 256 + threadIdx.x;
    g_csr[g_off[dstA[e]] + g_rank[e]] = e;
}

__global__ __launch_bounds__(512) void starts_kernel(const int* __restrict__ batch) {
    const int g = threadIdx.x;
    if (g > NG) return;
    int lo = 0, hi = NN;
    while (lo < hi) { int mid = (lo + hi) >> 1; if (batch[mid] < g) lo = mid + 1; else hi = mid; }
    g_starts[g] = lo;
}

// ---------------- P scatter ----------------
// P[v, d*IC+i] = sum_{e: dst=v} ea_aug[e,d] * xin[src[e], i]   for d in [0,33)
//   d<32: edge_attr, d=32: constant 1 (carries nn_b)
// tail block (last IC cols) = xin[v] itself (carries root_w)
template<int ICLOG>
__global__ __launch_bounds__(256)
void scatter_kernel(const float* __restrict__ xin, const float* __restrict__ eattr,
                    const int* __restrict__ srcA)
{
    constexpr int IC = 1 << ICLOG;
    constexpr int KB = 33 * IC;
    constexpr int KP = 34 * IC;
    constexpr int NT = (KB + 255) / 256;
    constexpr int CH = 8;
    __shared__ float xs[CH][IC];
    __shared__ float eas[CH][33];
    __shared__ int sed[CH], ssr[CH];
    const int v = blockIdx.x, t = threadIdx.x;
    const int s = g_off[v], e = g_off[v + 1];

    float acc[NT];
#pragma unroll
    for (int i = 0; i < NT; i++) acc[i] = 0.f;

    for (int base = s; base < e; base += CH) {
        const int m = min(CH, e - base);
        __syncthreads();
        if (t < m) { int ed = g_csr[base + t]; sed[t] = ed; ssr[t] = srcA[ed]; }
        __syncthreads();
        for (int idx = t; idx < m * 33; idx += 256) {
            int j = idx / 33, d = idx - j * 33;
            eas[j][d] = (d < 32) ? eattr[sed[j] * 32 + d] : 1.0f;
        }
        for (int idx = t; idx < m * IC; idx += 256) {
            int j = idx >> ICLOG, i = idx & (IC - 1);
            xs[j][i] = xin[(size_t)ssr[j] * IC + i];
        }
        __syncthreads();
#pragma unroll
        for (int ti = 0; ti < NT; ti++) {
            int k = t + ti * 256;
            if (k < KB) {
                int d = k >> ICLOG, i = k & (IC - 1);
                float a = acc[ti];
                for (int j = 0; j < m; j++) a = fmaf(eas[j][d], xs[j][i], a);
                acc[ti] = a;
            }
        }
    }
    float* __restrict__ row = g_P + (size_t)v * KP;
#pragma unroll
    for (int ti = 0; ti < NT; ti++) { int k = t + ti * 256; if (k < KB) row[k] = acc[ti]; }
    for (int k = KB + t; k < KP; k += 256) row[k] = xin[(size_t)v * IC + (k - KB)];
}

// ---------------- GEMM: out[4096,256] = P[4096,KP] @ [Wm;Wb;Wr] + bias ----------------
// B matrix row k: k<32IC -> Wm (nn_w, offset k*256), k<33IC -> Wb (nn_b), else Wr (root_w).
// BM=128, BN=64, BK=16, 128 threads, 8x8 microtile via packed fma.rn.f32x2.
// A stored pre-duplicated in smem as (a,a) u64 pairs -> inner loop is pure LDS.128 + FFMA2.
template<bool RELU>
__global__ __launch_bounds__(128)
void gemm_kernel(const float* __restrict__ P,
                 const float* __restrict__ Wm, const float* __restrict__ Wb,
                 const float* __restrict__ Wr, const float* __restrict__ bias,
                 float* __restrict__ out, int KP, int IC)
{
    __shared__ ull As2[16][128];   // 16 KB, duplicated pairs
    __shared__ float Bs[16][64];   // 4 KB
    const int t = threadIdx.x;
    const int ty = t >> 3, tx = t & 7;
    const int row0 = blockIdx.x * 128;
    const int col0 = blockIdx.y * 64;
    const int IC32 = IC * 32, IC33 = IC * 33;
    const float* Arow = P + (size_t)(row0 + t) * KP;

    ull acc[8][4];
#pragma unroll
    for (int r = 0; r < 8; r++)
#pragma unroll
        for (int c = 0; c < 4; c++) acc[r][c] = 0ull;

    float4 aA[4]; float4 aB[2];
    // prefetch tile 0
#pragma unroll
    for (int q = 0; q < 4; q++) aA[q] = *(const float4*)(Arow + q * 4);
#pragma unroll
    for (int q = 0; q < 2; q++) {
        int idx = 2 * t + q; int kr = idx >> 4; int o = col0 + (idx & 15) * 4;
        int k = kr;
        const float* p = (k < IC32) ? Wm + (size_t)k * 256 + o
                       : (k < IC33) ? Wb + (size_t)(k - IC32) * 256 + o
                                    : Wr + (size_t)(k - IC33) * 256 + o;
        aB[q] = *(const float4*)p;
    }

    const int NK = KP >> 4;
    for (int kt = 0; kt < NK; kt++) {
        __syncthreads();
        // store staged tile to smem (A duplicated)
#pragma unroll
        for (int q = 0; q < 4; q++) {
            As2[q * 4 + 0][t] = dup2(aA[q].x);
            As2[q * 4 + 1][t] = dup2(aA[q].y);
            As2[q * 4 + 2][t] = dup2(aA[q].z);
            As2[q * 4 + 3][t] = dup2(aA[q].w);
        }
#pragma unroll
        for (int q = 0; q < 2; q++) {
            int idx = 2 * t + q; int kr = idx >> 4; int c4 = (idx & 15) * 4;
            *(float4*)&Bs[kr][c4] = aB[q];
        }
        __syncthreads();
        // prefetch next tile (LDG latency hidden under compute)
        if (kt + 1 < NK) {
            const float* An = Arow + (size_t)(kt + 1) * 16;
#pragma unroll
            for (int q = 0; q < 4; q++) aA[q] = *(const float4*)(An + q * 4);
#pragma unroll
            for (int q = 0; q < 2; q++) {
                int idx = 2 * t + q; int kr = idx >> 4; int o = col0 + (idx & 15) * 4;
                int k = (kt + 1) * 16 + kr;
                const float* p = (k < IC32) ? Wm + (size_t)k * 256 + o
                               : (k < IC33) ? Wb + (size_t)(k - IC32) * 256 + o
                                            : Wr + (size_t)(k - IC33) * 256 + o;
                aB[q] = *(const float4*)p;
            }
        }
        // compute
#pragma unroll
        for (int kk = 0; kk < 16; kk++) {
            ull a2[8], b2[4];
            *(ulonglong2*)&a2[0] = *(const ulonglong2*)&As2[kk][ty * 8 + 0];
            *(ulonglong2*)&a2[2] = *(const ulonglong2*)&As2[kk][ty * 8 + 2];
            *(ulonglong2*)&a2[4] = *(const ulonglong2*)&As2[kk][ty * 8 + 4];
            *(ulonglong2*)&a2[6] = *(const ulonglong2*)&As2[kk][ty * 8 + 6];
            *(ulonglong2*)&b2[0] = *(const ulonglong2*)&Bs[kk][tx * 8 + 0];
            *(ulonglong2*)&b2[2] = *(const ulonglong2*)&Bs[kk][tx * 8 + 4];
#pragma unroll
            for (int r = 0; r < 8; r++)
#pragma unroll
                for (int c = 0; c < 4; c++)
                    acc[r][c] = ffma2(a2[r], b2[c], acc[r][c]);
        }
    }

    // epilogue: +bias, optional relu, vectorized store
    float4 bb0 = *(const float4*)(bias + col0 + tx * 8);
    float4 bb1 = *(const float4*)(bias + col0 + tx * 8 + 4);
#pragma unroll
    for (int r = 0; r < 8; r++) {
        int row = row0 + ty * 8 + r;
        float4 v0, v1;
        unpk(acc[r][0], v0.x, v0.y); unpk(acc[r][1], v0.z, v0.w);
        unpk(acc[r][2], v1.x, v1.y); unpk(acc[r][3], v1.z, v1.w);
        v0.x += bb0.x; v0.y += bb0.y; v0.z += bb0.z; v0.w += bb0.w;
        v1.x += bb1.x; v1.y += bb1.y; v1.z += bb1.z; v1.w += bb1.w;
        if (RELU) {
            v0.x = fmaxf(v0.x, 0.f); v0.y = fmaxf(v0.y, 0.f);
            v0.z = fmaxf(v0.z, 0.f); v0.w = fmaxf(v0.w, 0.f);
            v1.x = fmaxf(v1.x, 0.f); v1.y = fmaxf(v1.y, 0.f);
            v1.z = fmaxf(v1.z, 0.f); v1.w = fmaxf(v1.w, 0.f);
        }
        *(float4*)(out + (size_t)row * 256 + col0 + tx * 8)     = v0;
        *(float4*)(out + (size_t)row * 256 + col0 + tx * 8 + 4) = v1;
    }
}

// ---------------- mean pool + readout MLP + sigmoid ----------------
__global__ __launch_bounds__(256)
void pool_mlp_kernel(const float* __restrict__ l1w, const float* __restrict__ l1b,
                     const float* __restrict__ l2w, const float* __restrict__ l2b,
                     float* __restrict__ out)
{
    __shared__ float pooled[256];
    __shared__ float z[128];
    const int g = blockIdx.x, t = threadIdx.x;
    const int s = g_starts[g], e = g_starts[g + 1];
    float sum = 0.f;
    for (int r = s; r < e; r++) sum += g_h2[(size_t)r * 256 + t];
    float inv = 1.0f / (float)max(e - s, 1);
    pooled[t] = sum * inv;
    __syncthreads();
    if (t < 128) {
        float a = l1b[t];
        for (int o = 0; o < 256; o++) a = fmaf(pooled[o], l1w[o * 128 + t], a);
        z[t] = fmaxf(a, 0.f);
    }
    __syncthreads();
    if (t == 0) {
        float a = l2b[0];
        for (int j = 0; j < 128; j++) a = fmaf(z[j], l2w[j], a);
        out[g] = 1.0f / (1.0f + expf(-a));
    }
}

// ---------------- launch ----------------
extern "C" void kernel_launch(void* const* d_in, const int* in_sizes, int n_in,
                              void* d_out, int out_size)
{
    const float* x       = (const float*)d_in[0];
    const int*   ei      = (const int*)d_in[1];
    const float* ea      = (const float*)d_in[2];
    const int*   batch   = (const int*)d_in[3];
    const float* nn1_w   = (const float*)d_in[4];
    const float* nn1_b   = (const float*)d_in[5];
    const float* root1_w = (const float*)d_in[6];
    const float* bias1   = (const float*)d_in[7];
    const float* nn2_w   = (const float*)d_in[8];
    const float* nn2_b   = (const float*)d_in[9];
    const float* root2_w = (const float*)d_in[10];
    const float* bias2   = (const float*)d_in[11];
    const float* l1w     = (const float*)d_in[12];
    const float* l1b     = (const float*)d_in[13];
    const float* l2w     = (const float*)d_in[14];
    const float* l2b     = (const float*)d_in[15];
    const int* srcA = ei;
    const int* dstA = ei + NE;
    float* out = (float*)d_out;

    void *pP, *ph, *ph2;
    cudaGetSymbolAddress(&pP, g_P);
    cudaGetSymbolAddress(&ph, g_h);
    cudaGetSymbolAddress(&ph2, g_h2);

    zero_deg_kernel<<<16, 256>>>();
    rank_kernel<<<32, 256>>>(dstA);
    scan_kernel<<<1, 1024>>>();
    place_kernel<<<32, 256>>>(dstA);
    starts_kernel<<<1, 512>>>(batch);

    // conv1: IC=64, KP=2176
    scatter_kernel<6><<<NN, 256>>>(x, ea, srcA);
    gemm_kernel<true><<<dim3(32, 4), 128>>>((const float*)pP, nn1_w, nn1_b, root1_w, bias1,
                                            (float*)ph, 34 * 64, 64);
    // conv2: IC=256, KP=8704
    scatter_kernel<8><<<NN, 256>>>((const float*)ph, ea, srcA);
    gemm_kernel<false><<<dim3(32, 4), 128>>>((const float*)pP, nn2_w, nn2_b, root2_w, bias2,
                                             (float*)ph2, 34 * 256, 256);

    pool_mlp_kernel<<<NG, 256>>>(l1w, l1b, l2w, l2b, out);
}

// round 4
// speedup vs baseline: 2.9759x; 2.9759x over previous
#include <cuda_runtime.h>
#include <cuda_bf16.h>
#include <math.h>
#include <stdint.h>

typedef unsigned long long ull;

#define NN 4096
#define NE 8192
#define NG 256
#define OUTC 256

// ---------------- static device scratch ----------------
__device__ __nv_bfloat16 g_Ph[(size_t)NN * 8704];
__device__ __nv_bfloat16 g_Pl[(size_t)NN * 8704];
__device__ __nv_bfloat16 g_Wt1h[(size_t)256 * 2176];
__device__ __nv_bfloat16 g_Wt1l[(size_t)256 * 2176];
__device__ __nv_bfloat16 g_Wt2h[(size_t)256 * 8704];
__device__ __nv_bfloat16 g_Wt2l[(size_t)256 * 8704];
__device__ float g_h[NN * OUTC];
__device__ float g_h2[NN * OUTC];
__device__ int   g_deg[NN];
__device__ int   g_off[NN + 1];
__device__ int   g_rank[NE];
__device__ int   g_csr[NE];
__device__ int   g_starts[NG + 1];

// ---------------- helpers ----------------
__device__ __forceinline__ uint32_t smem_u32(const void* p) {
    uint32_t a;
    asm("{ .reg .u64 t; cvta.to.shared.u64 t, %1; cvt.u32.u64 %0, t; }" : "=r"(a) : "l"(p));
    return a;
}
__device__ __forceinline__ void cp16(uint32_t dst, const void* src) {
    asm volatile("cp.async.cg.shared.global [%0], [%1], 16;" :: "r"(dst), "l"(src) : "memory");
}
__device__ __forceinline__ void cp_commit() {
    asm volatile("cp.async.commit_group;" ::: "memory");
}
template<int N>
__device__ __forceinline__ void cp_wait() {
    asm volatile("cp.async.wait_group %0;" :: "n"(N) : "memory");
}
__device__ __forceinline__ void ldsm4(uint32_t* r, uint32_t addr) {
    asm volatile("ldmatrix.sync.aligned.m8n8.x4.shared.b16 {%0,%1,%2,%3}, [%4];"
                 : "=r"(r[0]), "=r"(r[1]), "=r"(r[2]), "=r"(r[3]) : "r"(addr));
}
__device__ __forceinline__ void mma16816(float* c, const uint32_t* a, const uint32_t* b) {
    asm volatile("mma.sync.aligned.m16n8k16.row.col.f32.bf16.bf16.f32 "
        "{%0,%1,%2,%3}, {%4,%5,%6,%7}, {%8,%9}, {%0,%1,%2,%3};"
        : "+f"(c[0]), "+f"(c[1]), "+f"(c[2]), "+f"(c[3])
        : "r"(a[0]), "r"(a[1]), "r"(a[2]), "r"(a[3]), "r"(b[0]), "r"(b[1]));
}
__device__ __forceinline__ void split_bf16(float v, __nv_bfloat16& h, __nv_bfloat16& l) {
    h = __float2bfloat16(v);
    l = __float2bfloat16(v - __bfloat162float(h));
}

// ---------------- deterministic CSR build ----------------
__global__ __launch_bounds__(256) void zero_deg_kernel() {
    int i = blockIdx.x * 256 + threadIdx.x;
    if (i < NN) g_deg[i] = 0;
}
__global__ __launch_bounds__(256) void rank_kernel(const int* __restrict__ dstA) {
    __shared__ int sd[NE];
    const int t = threadIdx.x;
    for (int i = t; i < NE; i += 256) sd[i] = dstA[i];
    __syncthreads();
    const int e = blockIdx.x * 256 + t;
    const int de = sd[e];
    int r = 0;
    for (int j = 0; j < e; j++) r += (sd[j] == de) ? 1 : 0;
    g_rank[e] = r;
    atomicAdd(&g_deg[de], 1);
}
__global__ __launch_bounds__(1024) void scan_kernel() {
    __shared__ int s[1024];
    const int t = threadIdx.x;
    int l0 = g_deg[4 * t + 0], l1 = g_deg[4 * t + 1];
    int l2 = g_deg[4 * t + 2], l3 = g_deg[4 * t + 3];
    int tot = l0 + l1 + l2 + l3;
    s[t] = tot;
    __syncthreads();
    for (int off = 1; off < 1024; off <<= 1) {
        int v = (t >= off) ? s[t - off] : 0;
        __syncthreads();
        s[t] += v;
        __syncthreads();
    }
    int excl = s[t] - tot;
    g_off[4 * t + 0] = excl;
    g_off[4 * t + 1] = excl + l0;
    g_off[4 * t + 2] = excl + l0 + l1;
    g_off[4 * t + 3] = excl + l0 + l1 + l2;
    if (t == 1023) g_off[NN] = excl + tot;
}
__global__ __launch_bounds__(256) void place_kernel(const int* __restrict__ dstA) {
    const int e = blockIdx.x * 256 + threadIdx.x;
    g_csr[g_off[dstA[e]] + g_rank[e]] = e;
}
__global__ __launch_bounds__(512) void starts_kernel(const int* __restrict__ batch) {
    const int g = threadIdx.x;
    if (g > NG) return;
    int lo = 0, hi = NN;
    while (lo < hi) { int mid = (lo + hi) >> 1; if (batch[mid] < g) lo = mid + 1; else hi = mid; }
    g_starts[g] = lo;
}

// ---------------- weight prep: transpose + bf16 hi/lo split ----------------
__global__ __launch_bounds__(256)
void prep_kernel(const float* __restrict__ Wm1, const float* __restrict__ Wb1, const float* __restrict__ Wr1,
                 const float* __restrict__ Wm2, const float* __restrict__ Wb2, const float* __restrict__ Wr2)
{
    const int conv = blockIdx.z;
    const int KP = conv ? 8704 : 2176;
    const int IC = conv ? 256 : 64;
    const int k0 = blockIdx.x * 32;
    if (k0 >= KP) return;
    const int o0 = blockIdx.y * 32;
    const float* Wm = conv ? Wm2 : Wm1;
    const float* Wb = conv ? Wb2 : Wb1;
    const float* Wr = conv ? Wr2 : Wr1;
    __nv_bfloat16* Th = conv ? g_Wt2h : g_Wt1h;
    __nv_bfloat16* Tl = conv ? g_Wt2l : g_Wt1l;
    const int IC32 = IC * 32, IC33 = IC * 33;
    __shared__ float tile[32][33];
    const int tx = threadIdx.x & 31, ty = threadIdx.x >> 5;
#pragma unroll
    for (int rr = 0; rr < 4; rr++) {
        int k = k0 + ty + rr * 8;
        const float* p = (k < IC32) ? Wm + (size_t)k * 256 + o0 + tx
                       : (k < IC33) ? Wb + (size_t)(k - IC32) * 256 + o0 + tx
                                    : Wr + (size_t)(k - IC33) * 256 + o0 + tx;
        tile[ty + rr * 8][tx] = *p;
    }
    __syncthreads();
#pragma unroll
    for (int rr = 0; rr < 4; rr++) {
        int o = o0 + ty + rr * 8;
        float v = tile[tx][ty + rr * 8];
        __nv_bfloat16 h, l; split_bf16(v, h, l);
        Th[(size_t)o * KP + k0 + tx] = h;
        Tl[(size_t)o * KP + k0 + tx] = l;
    }
}

// ---------------- P scatter (bf16 hi/lo output) ----------------
template<int ICLOG>
__global__ __launch_bounds__(256)
void scatter_kernel(const float* __restrict__ xin, const float* __restrict__ eattr,
                    const int* __restrict__ srcA)
{
    constexpr int IC = 1 << ICLOG;
    constexpr int KB = 33 * IC;
    constexpr int KP = 34 * IC;
    constexpr int NT = (KB + 255) / 256;
    constexpr int CH = 8;
    __shared__ float xs[CH][IC];
    __shared__ float eas[CH][33];
    __shared__ int sed[CH], ssr[CH];
    const int v = blockIdx.x, t = threadIdx.x;
    const int s = g_off[v], e = g_off[v + 1];

    float acc[NT];
#pragma unroll
    for (int i = 0; i < NT; i++) acc[i] = 0.f;

    for (int base = s; base < e; base += CH) {
        const int m = min(CH, e - base);
        __syncthreads();
        if (t < m) { int ed = g_csr[base + t]; sed[t] = ed; ssr[t] = srcA[ed]; }
        __syncthreads();
        for (int idx = t; idx < m * 33; idx += 256) {
            int j = idx / 33, d = idx - j * 33;
            eas[j][d] = (d < 32) ? eattr[sed[j] * 32 + d] : 1.0f;
        }
        for (int idx = t; idx < m * IC; idx += 256) {
            int j = idx >> ICLOG, i = idx & (IC - 1);
            xs[j][i] = xin[(size_t)ssr[j] * IC + i];
        }
        __syncthreads();
#pragma unroll
        for (int ti = 0; ti < NT; ti++) {
            int k = t + ti * 256;
            if (k < KB) {
                int d = k >> ICLOG, i = k & (IC - 1);
                float a = acc[ti];
                for (int j = 0; j < m; j++) a = fmaf(eas[j][d], xs[j][i], a);
                acc[ti] = a;
            }
        }
    }
    __nv_bfloat16* rh = g_Ph + (size_t)v * KP;
    __nv_bfloat16* rl = g_Pl + (size_t)v * KP;
#pragma unroll
    for (int ti = 0; ti < NT; ti++) {
        int k = t + ti * 256;
        if (k < KB) { __nv_bfloat16 h, l; split_bf16(acc[ti], h, l); rh[k] = h; rl[k] = l; }
    }
    for (int k = KB + t; k < KP; k += 256) {
        float vv = xin[(size_t)v * IC + (k - KB)];
        __nv_bfloat16 h, l; split_bf16(vv, h, l); rh[k] = h; rl[k] = l;
    }
}

// ---------------- mma.sync GEMM: out[4096,256] = (Ph+Pl) @ Wt^T + bias ----------------
// BM=128, BN=64, BK=32, 256 threads (8 warps 4x2, warp tile 32x32).
// 3-term bf16 split: AhBh + AlBh + AhBl. 3-stage cp.async pipeline.
// Stage layout (24576 B): Ah[128][32] @0, Al @8192, Bh[64][32] @16384, Bl @20480.
// Swizzle: 16B chunk' = chunk ^ ((row>>1)&3)   (row stride 64 B).
#define STG_BYTES 24576
#define GEMM_SMEM (3 * STG_BYTES)

template<int KP, bool RELU>
__global__ __launch_bounds__(256, 1)
void gemm_mma(const __nv_bfloat16* __restrict__ Ah, const __nv_bfloat16* __restrict__ Al,
              const __nv_bfloat16* __restrict__ Bh, const __nv_bfloat16* __restrict__ Bl,
              const float* __restrict__ bias, float* __restrict__ out)
{
    static_assert(KP % 32 == 0, "");
    constexpr int NK = KP / 32;
    extern __shared__ char smem[];
    const uint32_t sb = smem_u32(smem);
    const int t = threadIdx.x, lane = t & 31, wid = t >> 5;
    const int row0 = blockIdx.x * 128, col0 = blockIdx.y * 64;
    const int wm = (wid & 3) * 32, wn = (wid >> 2) * 32;

    float acc[2][4][4];
#pragma unroll
    for (int mf = 0; mf < 2; mf++)
#pragma unroll
        for (int nf = 0; nf < 4; nf++)
#pragma unroll
            for (int i = 0; i < 4; i++) acc[mf][nf][i] = 0.f;

    // precomputed ldmatrix addresses (relative to stage base)
    uint32_t a_addr[2][2], b_addr[2][2];
#pragma unroll
    for (int mf = 0; mf < 2; mf++)
#pragma unroll
        for (int g = 0; g < 2; g++) {
            int r = wm + mf * 16 + (lane & 7) + ((lane >> 3) & 1) * 8;
            int c = 2 * g + (lane >> 4);
            a_addr[mf][g] = (uint32_t)(r * 64 + ((c ^ ((r >> 1) & 3)) * 16));
        }
#pragma unroll
    for (int np = 0; np < 2; np++)
#pragma unroll
        for (int g = 0; g < 2; g++) {
            int r = wn + np * 16 + (lane & 7) + ((lane >> 4) & 1) * 8;
            int c = 2 * g + ((lane >> 3) & 1);
            b_addr[np][g] = (uint32_t)(16384 + r * 64 + ((c ^ ((r >> 1) & 3)) * 16));
        }

    // cp.async source/dest mapping
    const int ar0 = t >> 2;              // A rows: t/4 and t/4 + 64
    const int ac  = t & 3;
    const int br  = t >> 2;              // B row (0..63)
    const uint32_t adst0 = (uint32_t)(ar0 * 64 + ((ac ^ ((ar0 >> 1) & 3)) * 16));
    const int ar1 = ar0 + 64;
    const uint32_t adst1 = (uint32_t)(ar1 * 64 + ((ac ^ ((ar1 >> 1) & 3)) * 16));
    const uint32_t bdst  = (uint32_t)(16384 + br * 64 + ((ac ^ ((br >> 1) & 3)) * 16));
    const __nv_bfloat16* gah0 = Ah + (size_t)(row0 + ar0) * KP + ac * 8;
    const __nv_bfloat16* gah1 = Ah + (size_t)(row0 + ar1) * KP + ac * 8;
    const __nv_bfloat16* gal0 = Al + (size_t)(row0 + ar0) * KP + ac * 8;
    const __nv_bfloat16* gal1 = Al + (size_t)(row0 + ar1) * KP + ac * 8;
    const __nv_bfloat16* gbh  = Bh + (size_t)(col0 + br) * KP + ac * 8;
    const __nv_bfloat16* gbl  = Bl + (size_t)(col0 + br) * KP + ac * 8;

#define LOAD_STAGE(KT, S) do {                                   \
    uint32_t _sb = sb + (S) * STG_BYTES;                         \
    int _ko = (KT) * 32;                                         \
    cp16(_sb + adst0,        gah0 + _ko);                        \
    cp16(_sb + adst1,        gah1 + _ko);                        \
    cp16(_sb + adst0 + 8192, gal0 + _ko);                        \
    cp16(_sb + adst1 + 8192, gal1 + _ko);                        \
    cp16(_sb + bdst,         gbh + _ko);                         \
    cp16(_sb + bdst + 4096,  gbl + _ko);                         \
    cp_commit();                                                 \
} while (0)

    LOAD_STAGE(0, 0);
    LOAD_STAGE(1, 1);
    LOAD_STAGE(2, 2);

    int stage = 0;
    for (int kt = 0; kt < NK; kt++) {
        cp_wait<2>();
        __syncthreads();
        const uint32_t sbase = sb + stage * STG_BYTES;
#pragma unroll
        for (int g = 0; g < 2; g++) {
            uint32_t ah[2][4], al[2][4], bh[2][4], bl[2][4];
#pragma unroll
            for (int mf = 0; mf < 2; mf++) {
                ldsm4(ah[mf], sbase + a_addr[mf][g]);
                ldsm4(al[mf], sbase + a_addr[mf][g] + 8192);
            }
#pragma unroll
            for (int np = 0; np < 2; np++) {
                ldsm4(bh[np], sbase + b_addr[np][g]);
                ldsm4(bl[np], sbase + b_addr[np][g] + 4096);
            }
#pragma unroll
            for (int mf = 0; mf < 2; mf++)
#pragma unroll
                for (int nf = 0; nf < 4; nf++) {
                    const uint32_t* ph = &bh[nf >> 1][(nf & 1) * 2];
                    const uint32_t* pl = &bl[nf >> 1][(nf & 1) * 2];
                    mma16816(acc[mf][nf], ah[mf], ph);
                    mma16816(acc[mf][nf], al[mf], ph);
                    mma16816(acc[mf][nf], ah[mf], pl);
                }
        }
        __syncthreads();
        if (kt + 3 < NK) LOAD_STAGE(kt + 3, stage);
        else cp_commit();
        stage = (stage == 2) ? 0 : stage + 1;
    }
#undef LOAD_STAGE

    // epilogue
#pragma unroll
    for (int mf = 0; mf < 2; mf++) {
        const int r0 = row0 + wm + mf * 16 + (lane >> 2);
#pragma unroll
        for (int nf = 0; nf < 4; nf++) {
            const int c = col0 + wn + nf * 8 + (lane & 3) * 2;
            float b0 = bias[c], b1 = bias[c + 1];
            float2 v0 = make_float2(acc[mf][nf][0] + b0, acc[mf][nf][1] + b1);
            float2 v1 = make_float2(acc[mf][nf][2] + b0, acc[mf][nf][3] + b1);
            if (RELU) {
                v0.x = fmaxf(v0.x, 0.f); v0.y = fmaxf(v0.y, 0.f);
                v1.x = fmaxf(v1.x, 0.f); v1.y = fmaxf(v1.y, 0.f);
            }
            *(float2*)(out + (size_t)r0 * 256 + c)       = v0;
            *(float2*)(out + (size_t)(r0 + 8) * 256 + c) = v1;
        }
    }
}

// ---------------- mean pool + readout MLP + sigmoid ----------------
__global__ __launch_bounds__(256)
void pool_mlp_kernel(const float* __restrict__ l1w, const float* __restrict__ l1b,
                     const float* __restrict__ l2w, const float* __restrict__ l2b,
                     float* __restrict__ out)
{
    __shared__ float pooled[256];
    __shared__ float z[128];
    const int g = blockIdx.x, t = threadIdx.x;
    const int s = g_starts[g], e = g_starts[g + 1];
    float sum = 0.f;
    for (int r = s; r < e; r++) sum += g_h2[(size_t)r * 256 + t];
    float inv = 1.0f / (float)max(e - s, 1);
    pooled[t] = sum * inv;
    __syncthreads();
    if (t < 128) {
        float a = l1b[t];
        for (int o = 0; o < 256; o++) a = fmaf(pooled[o], l1w[o * 128 + t], a);
        z[t] = fmaxf(a, 0.f);
    }
    __syncthreads();
    if (t == 0) {
        float a = l2b[0];
        for (int j = 0; j < 128; j++) a = fmaf(z[j], l2w[j], a);
        out[g] = 1.0f / (1.0f + expf(-a));
    }
}

// ---------------- launch ----------------
extern "C" void kernel_launch(void* const* d_in, const int* in_sizes, int n_in,
                              void* d_out, int out_size)
{
    const float* x       = (const float*)d_in[0];
    const int*   ei      = (const int*)d_in[1];
    const float* ea      = (const float*)d_in[2];
    const int*   batch   = (const int*)d_in[3];
    const float* nn1_w   = (const float*)d_in[4];
    const float* nn1_b   = (const float*)d_in[5];
    const float* root1_w = (const float*)d_in[6];
    const float* bias1   = (const float*)d_in[7];
    const float* nn2_w   = (const float*)d_in[8];
    const float* nn2_b   = (const float*)d_in[9];
    const float* root2_w = (const float*)d_in[10];
    const float* bias2   = (const float*)d_in[11];
    const float* l1w     = (const float*)d_in[12];
    const float* l1b     = (const float*)d_in[13];
    const float* l2w     = (const float*)d_in[14];
    const float* l2b     = (const float*)d_in[15];
    const int* srcA = ei;
    const int* dstA = ei + NE;
    float* out = (float*)d_out;

    void *pPh, *pPl, *pW1h, *pW1l, *pW2h, *pW2l, *ph, *ph2;
    cudaGetSymbolAddress(&pPh, g_Ph);
    cudaGetSymbolAddress(&pPl, g_Pl);
    cudaGetSymbolAddress(&pW1h, g_Wt1h);
    cudaGetSymbolAddress(&pW1l, g_Wt1l);
    cudaGetSymbolAddress(&pW2h, g_Wt2h);
    cudaGetSymbolAddress(&pW2l, g_Wt2l);
    cudaGetSymbolAddress(&ph, g_h);
    cudaGetSymbolAddress(&ph2, g_h2);

    cudaFuncSetAttribute(gemm_mma<2176, true>,  cudaFuncAttributeMaxDynamicSharedMemorySize, GEMM_SMEM);
    cudaFuncSetAttribute(gemm_mma<8704, false>, cudaFuncAttributeMaxDynamicSharedMemorySize, GEMM_SMEM);

    zero_deg_kernel<<<16, 256>>>();
    rank_kernel<<<32, 256>>>(dstA);
    scan_kernel<<<1, 1024>>>();
    place_kernel<<<32, 256>>>(dstA);
    starts_kernel<<<1, 512>>>(batch);
    prep_kernel<<<dim3(272, 8, 2), 256>>>(nn1_w, nn1_b, root1_w, nn2_w, nn2_b, root2_w);

    // conv1
    scatter_kernel<6><<<NN, 256>>>(x, ea, srcA);
    gemm_mma<2176, true><<<dim3(32, 4), 256, GEMM_SMEM>>>(
        (const __nv_bfloat16*)pPh, (const __nv_bfloat16*)pPl,
        (const __nv_bfloat16*)pW1h, (const __nv_bfloat16*)pW1l, bias1, (float*)ph);
    // conv2
    scatter_kernel<8><<<NN, 256>>>((const float*)ph, ea, srcA);
    gemm_mma<8704, false><<<dim3(32, 4), 256, GEMM_SMEM>>>(
        (const __nv_bfloat16*)pPh, (const __nv_bfloat16*)pPl,
        (const __nv_bfloat16*)pW2h, (const __nv_bfloat16*)pW2l, bias2, (float*)ph2);

    pool_mlp_kernel<<<NG, 256>>>(l1w, l1b, l2w, l2b, out);
}

// round 7
// speedup vs baseline: 4.0390x; 1.3572x over previous
#include <cuda_runtime.h>
#include <cuda_fp16.h>
#include <math.h>
#include <stdint.h>

#define NN 4096
#define NE 8192
#define NG 256
#define OUTC 256

// ---------------- static device scratch ----------------
__device__ __half g_Ph[(size_t)NN * 8704];
__device__ __half g_Pl[(size_t)NN * 8704];
__device__ __half g_Wt1[(size_t)256 * 2176];
__device__ __half g_Wt2[(size_t)256 * 8704];
__device__ float g_h[NN * OUTC];
__device__ float g_h2[NN * OUTC];
__device__ int   g_deg[NN];
__device__ int   g_off[NN + 1];
__device__ int   g_rank[NE];
__device__ int   g_csr[NE];
__device__ int   g_starts[NG + 1];

// ---------------- helpers ----------------
__device__ __forceinline__ uint32_t smem_u32(const void* p) {
    uint32_t a;
    asm("{ .reg .u64 t; cvta.to.shared.u64 t, %1; cvt.u32.u64 %0, t; }" : "=r"(a) : "l"(p));
    return a;
}
__device__ __forceinline__ void cp16(uint32_t dst, const void* src) {
    asm volatile("cp.async.cg.shared.global [%0], [%1], 16;" :: "r"(dst), "l"(src) : "memory");
}
__device__ __forceinline__ void cp_commit() {
    asm volatile("cp.async.commit_group;" ::: "memory");
}
template<int N>
__device__ __forceinline__ void cp_wait() {
    asm volatile("cp.async.wait_group %0;" :: "n"(N) : "memory");
}
__device__ __forceinline__ void ldsm4(uint32_t* r, uint32_t addr) {
    asm volatile("ldmatrix.sync.aligned.m8n8.x4.shared.b16 {%0,%1,%2,%3}, [%4];"
                 : "=r"(r[0]), "=r"(r[1]), "=r"(r[2]), "=r"(r[3]) : "r"(addr));
}
__device__ __forceinline__ void mma16816h(float* c, const uint32_t* a, const uint32_t* b) {
    asm volatile("mma.sync.aligned.m16n8k16.row.col.f32.f16.f16.f32 "
        "{%0,%1,%2,%3}, {%4,%5,%6,%7}, {%8,%9}, {%0,%1,%2,%3};"
        : "+f"(c[0]), "+f"(c[1]), "+f"(c[2]), "+f"(c[3])
        : "r"(a[0]), "r"(a[1]), "r"(a[2]), "r"(a[3]), "r"(b[0]), "r"(b[1]));
}
__device__ __forceinline__ uint32_t pack2h(__half a, __half b) {
    __half2 h = __halves2half2(a, b);
    return *(uint32_t*)&h;
}

// ---------------- deterministic CSR build ----------------
__global__ __launch_bounds__(256) void zero_deg_kernel() {
    int i = blockIdx.x * 256 + threadIdx.x;
    if (i < NN) g_deg[i] = 0;
}
__global__ __launch_bounds__(256) void rank_kernel(const int* __restrict__ dstA) {
    __shared__ int sd[NE];
    const int t = threadIdx.x;
    for (int i = t; i < NE; i += 256) sd[i] = dstA[i];
    __syncthreads();
    const int e = blockIdx.x * 256 + t;
    const int de = sd[e];
    int r = 0, j = 0;
    for (; j + 1 < e; j += 2) {
        int2 v = *(const int2*)&sd[j];
        r += (v.x == de) ? 1 : 0;
        r += (v.y == de) ? 1 : 0;
    }
    if (j < e) r += (sd[j] == de) ? 1 : 0;
    g_rank[e] = r;
    atomicAdd(&g_deg[de], 1);
}
__global__ __launch_bounds__(1024) void scan_kernel() {
    __shared__ int s[1024];
    const int t = threadIdx.x;
    int l0 = g_deg[4 * t + 0], l1 = g_deg[4 * t + 1];
    int l2 = g_deg[4 * t + 2], l3 = g_deg[4 * t + 3];
    int tot = l0 + l1 + l2 + l3;
    s[t] = tot;
    __syncthreads();
    for (int off = 1; off < 1024; off <<= 1) {
        int v = (t >= off) ? s[t - off] : 0;
        __syncthreads();
        s[t] += v;
        __syncthreads();
    }
    int excl = s[t] - tot;
    g_off[4 * t + 0] = excl;
    g_off[4 * t + 1] = excl + l0;
    g_off[4 * t + 2] = excl + l0 + l1;
    g_off[4 * t + 3] = excl + l0 + l1 + l2;
    if (t == 1023) g_off[NN] = excl + tot;
}
__global__ __launch_bounds__(256) void place_kernel(const int* __restrict__ dstA) {
    const int e = blockIdx.x * 256 + threadIdx.x;
    g_csr[g_off[dstA[e]] + g_rank[e]] = e;
}
__global__ __launch_bounds__(512) void starts_kernel(const int* __restrict__ batch) {
    const int g = threadIdx.x;
    if (g > NG) return;
    int lo = 0, hi = NN;
    while (lo < hi) { int mid = (lo + hi) >> 1; if (batch[mid] < g) lo = mid + 1; else hi = mid; }
    g_starts[g] = lo;
}

// ---------------- weight prep: transpose + fp16 ----------------
// Wt[o][k] = Bstack[k][o]; row k: k<32IC nn_w, k<33IC nn_b, else root_w.
__global__ __launch_bounds__(256)
void prep_kernel(const float* __restrict__ Wm1, const float* __restrict__ Wb1, const float* __restrict__ Wr1,
                 const float* __restrict__ Wm2, const float* __restrict__ Wb2, const float* __restrict__ Wr2)
{
    const int conv = blockIdx.z;
    const int KP = conv ? 8704 : 2176;
    const int IC = conv ? 256 : 64;
    const int k0 = blockIdx.x * 32;
    if (k0 >= KP) return;
    const int o0 = blockIdx.y * 32;
    const float* Wm = conv ? Wm2 : Wm1;
    const float* Wb = conv ? Wb2 : Wb1;
    const float* Wr = conv ? Wr2 : Wr1;
    __half* Th = conv ? g_Wt2 : g_Wt1;
    const int IC32 = IC * 32, IC33 = IC * 33;
    __shared__ float tile[32][33];
    const int tx = threadIdx.x & 31, ty = threadIdx.x >> 5;
#pragma unroll
    for (int rr = 0; rr < 4; rr++) {
        int k = k0 + ty + rr * 8;
        const float* p = (k < IC32) ? Wm + (size_t)k * 256 + o0 + tx
                       : (k < IC33) ? Wb + (size_t)(k - IC32) * 256 + o0 + tx
                                    : Wr + (size_t)(k - IC33) * 256 + o0 + tx;
        tile[ty + rr * 8][tx] = *p;
    }
    __syncthreads();
#pragma unroll
    for (int rr = 0; rr < 4; rr++) {
        int o = o0 + ty + rr * 8;
        Th[(size_t)o * KP + k0 + tx] = __float2half_rn(tile[tx][ty + rr * 8]);
    }
}

// ---------------- P scatter (fp16 hi/lo, vectorized stores) ----------------
template<int ICLOG>
__global__ __launch_bounds__(256)
void scatter_kernel(const float* __restrict__ xin, const float* __restrict__ eattr,
                    const int* __restrict__ srcA)
{
    constexpr int IC = 1 << ICLOG;
    constexpr int KB = 33 * IC;
    constexpr int KP = 34 * IC;
    constexpr int NT = (KB + 255) / 256;
    constexpr int CH = 8;
    __shared__ float xs[CH][IC];
    __shared__ float eas[CH][33];
    __shared__ float st[KB];
    __shared__ int sed[CH], ssr[CH];
    const int v = blockIdx.x, t = threadIdx.x;
    const int s = g_off[v], e = g_off[v + 1];

    float acc[NT];
#pragma unroll
    for (int i = 0; i < NT; i++) acc[i] = 0.f;

    for (int base = s; base < e; base += CH) {
        const int m = min(CH, e - base);
        __syncthreads();
        if (t < m) { int ed = g_csr[base + t]; sed[t] = ed; ssr[t] = srcA[ed]; }
        __syncthreads();
        for (int idx = t; idx < m * 33; idx += 256) {
            int j = idx / 33, d = idx - j * 33;
            eas[j][d] = (d < 32) ? eattr[sed[j] * 32 + d] : 1.0f;
        }
        for (int idx = t; idx < m * IC; idx += 256) {
            int j = idx >> ICLOG, i = idx & (IC - 1);
            xs[j][i] = xin[(size_t)ssr[j] * IC + i];
        }
        __syncthreads();
#pragma unroll
        for (int ti = 0; ti < NT; ti++) {
            int k = t + ti * 256;
            if (k < KB) {
                int d = k >> ICLOG, i = k & (IC - 1);
                float a = acc[ti];
                for (int j = 0; j < m; j++) a = fmaf(eas[j][d], xs[j][i], a);
                acc[ti] = a;
            }
        }
    }
    // stage accumulators, then vectorized hi/lo stores
#pragma unroll
    for (int ti = 0; ti < NT; ti++) {
        int k = t + ti * 256;
        if (k < KB) st[k] = acc[ti];
    }
    __syncthreads();
    __half* rh = g_Ph + (size_t)v * KP;
    __half* rl = g_Pl + (size_t)v * KP;
    for (int idx = t; idx < KB / 8; idx += 256) {
        const float* f = &st[idx * 8];
        __half hh[8]; uint4 hv, lv;
#pragma unroll
        for (int i = 0; i < 8; i++) hh[i] = __float2half_rn(f[i]);
        hv.x = pack2h(hh[0], hh[1]); hv.y = pack2h(hh[2], hh[3]);
        hv.z = pack2h(hh[4], hh[5]); hv.w = pack2h(hh[6], hh[7]);
        __half ll[8];
#pragma unroll
        for (int i = 0; i < 8; i++) ll[i] = __float2half_rn(f[i] - __half2float(hh[i]));
        lv.x = pack2h(ll[0], ll[1]); lv.y = pack2h(ll[2], ll[3]);
        lv.z = pack2h(ll[4], ll[5]); lv.w = pack2h(ll[6], ll[7]);
        *(uint4*)(rh + idx * 8) = hv;
        *(uint4*)(rl + idx * 8) = lv;
    }
    // tail block: x[v] itself (root transform)
    const float* xrow = xin + (size_t)v * IC;
    for (int idx = t; idx < IC / 8; idx += 256) {
        const float* f = xrow + idx * 8;
        __half hh[8]; uint4 hv, lv;
#pragma unroll
        for (int i = 0; i < 8; i++) hh[i] = __float2half_rn(f[i]);
        hv.x = pack2h(hh[0], hh[1]); hv.y = pack2h(hh[2], hh[3]);
        hv.z = pack2h(hh[4], hh[5]); hv.w = pack2h(hh[6], hh[7]);
        __half ll[8];
#pragma unroll
        for (int i = 0; i < 8; i++) ll[i] = __float2half_rn(f[i] - __half2float(hh[i]));
        lv.x = pack2h(ll[0], ll[1]); lv.y = pack2h(ll[2], ll[3]);
        lv.z = pack2h(ll[4], ll[5]); lv.w = pack2h(ll[6], ll[7]);
        *(uint4*)(rh + KB + idx * 8) = hv;
        *(uint4*)(rl + KB + idx * 8) = lv;
    }
}

// ---------------- mma.sync GEMM (fp16, 2-term): out = (Ah+Al) @ Wt^T + bias ----------------
// BM=128, BN=64, BK=32, 256 threads (8 warps 4x2, warp tile 32x32).
// Stage (20480 B): Ah[128][32] @0, Al @8192, B[64][32] @16384. 4-stage cp.async, 1 sync/iter.
// Swizzle: 16B chunk' = chunk ^ ((row>>1)&3) (row stride 64 B).
#define STG_BYTES 20480
#define GEMM_SMEM (4 * STG_BYTES)

template<int KP, bool RELU>
__global__ __launch_bounds__(256, 1)
void gemm_mma(const __half* __restrict__ Ah, const __half* __restrict__ Al,
              const __half* __restrict__ B, const float* __restrict__ bias,
              float* __restrict__ out)
{
    static_assert(KP % 32 == 0, "");
    constexpr int NK = KP / 32;
    extern __shared__ char smem[];
    const uint32_t sb = smem_u32(smem);
    const int t = threadIdx.x, lane = t & 31, wid = t >> 5;
    const int row0 = blockIdx.x * 128, col0 = blockIdx.y * 64;
    const int wm = (wid & 3) * 32, wn = (wid >> 2) * 32;

    float acc[2][4][4];
#pragma unroll
    for (int mf = 0; mf < 2; mf++)
#pragma unroll
        for (int nf = 0; nf < 4; nf++)
#pragma unroll
            for (int i = 0; i < 4; i++) acc[mf][nf][i] = 0.f;

    uint32_t a_addr[2][2], b_addr[2][2];
#pragma unroll
    for (int mf = 0; mf < 2; mf++)
#pragma unroll
        for (int g = 0; g < 2; g++) {
            int r = wm + mf * 16 + (lane & 7) + ((lane >> 3) & 1) * 8;
            int c = 2 * g + (lane >> 4);
            a_addr[mf][g] = (uint32_t)(r * 64 + ((c ^ ((r >> 1) & 3)) * 16));
        }
#pragma unroll
    for (int np = 0; np < 2; np++)
#pragma unroll
        for (int g = 0; g < 2; g++) {
            int r = wn + np * 16 + (lane & 7) + ((lane >> 4) & 1) * 8;
            int c = 2 * g + ((lane >> 3) & 1);
            b_addr[np][g] = (uint32_t)(16384 + r * 64 + ((c ^ ((r >> 1) & 3)) * 16));
        }

    const int ar0 = t >> 2;
    const int ac  = t & 3;
    const int br  = t >> 2;
    const uint32_t adst0 = (uint32_t)(ar0 * 64 + ((ac ^ ((ar0 >> 1) & 3)) * 16));
    const int ar1 = ar0 + 64;
    const uint32_t adst1 = (uint32_t)(ar1 * 64 + ((ac ^ ((ar1 >> 1) & 3)) * 16));
    const uint32_t bdst  = (uint32_t)(16384 + br * 64 + ((ac ^ ((br >> 1) & 3)) * 16));
    const __half* gah0 = Ah + (size_t)(row0 + ar0) * KP + ac * 8;
    const __half* gah1 = Ah + (size_t)(row0 + ar1) * KP + ac * 8;
    const __half* gal0 = Al + (size_t)(row0 + ar0) * KP + ac * 8;
    const __half* gal1 = Al + (size_t)(row0 + ar1) * KP + ac * 8;
    const __half* gb   = B  + (size_t)(col0 + br) * KP + ac * 8;

#define LOAD_STAGE(KT, S) do {                                   \
    uint32_t _sb = sb + (S) * STG_BYTES;                         \
    int _ko = (KT) * 32;                                         \
    cp16(_sb + adst0,        gah0 + _ko);                        \
    cp16(_sb + adst1,        gah1 + _ko);                        \
    cp16(_sb + adst0 + 8192, gal0 + _ko);                        \
    cp16(_sb + adst1 + 8192, gal1 + _ko);                        \
    cp16(_sb + bdst,         gb + _ko);                          \
    cp_commit();                                                 \
} while (0)

    LOAD_STAGE(0, 0);
    LOAD_STAGE(1, 1);
    LOAD_STAGE(2, 2);

    for (int kt = 0; kt < NK; kt++) {
        cp_wait<2>();
        __syncthreads();
        const uint32_t sbase = sb + (kt & 3) * STG_BYTES;
#pragma unroll
        for (int g = 0; g < 2; g++) {
            uint32_t ah[2][4], al[2][4], bh[2][4];
#pragma unroll
            for (int mf = 0; mf < 2; mf++) {
                ldsm4(ah[mf], sbase + a_addr[mf][g]);
                ldsm4(al[mf], sbase + a_addr[mf][g] + 8192);
            }
#pragma unroll
            for (int np = 0; np < 2; np++) ldsm4(bh[np], sbase + b_addr[np][g]);
#pragma unroll
            for (int mf = 0; mf < 2; mf++)
#pragma unroll
                for (int nf = 0; nf < 4; nf++) {
                    const uint32_t* pb = &bh[nf >> 1][(nf & 1) * 2];
                    mma16816h(acc[mf][nf], ah[mf], pb);
                    mma16816h(acc[mf][nf], al[mf], pb);
                }
        }
        if (kt + 3 < NK) LOAD_STAGE(kt + 3, (kt + 3) & 3);
        else cp_commit();
    }
#undef LOAD_STAGE

#pragma unroll
    for (int mf = 0; mf < 2; mf++) {
        const int r0 = row0 + wm + mf * 16 + (lane >> 2);
#pragma unroll
        for (int nf = 0; nf < 4; nf++) {
            const int c = col0 + wn + nf * 8 + (lane & 3) * 2;
            float b0 = bias[c], b1 = bias[c + 1];
            float2 v0 = make_float2(acc[mf][nf][0] + b0, acc[mf][nf][1] + b1);
            float2 v1 = make_float2(acc[mf][nf][2] + b0, acc[mf][nf][3] + b1);
            if (RELU) {
                v0.x = fmaxf(v0.x, 0.f); v0.y = fmaxf(v0.y, 0.f);
                v1.x = fmaxf(v1.x, 0.f); v1.y = fmaxf(v1.y, 0.f);
            }
            *(float2*)(out + (size_t)r0 * 256 + c)       = v0;
            *(float2*)(out + (size_t)(r0 + 8) * 256 + c) = v1;
        }
    }
}

// ---------------- mean pool + readout MLP + sigmoid ----------------
__global__ __launch_bounds__(256)
void pool_mlp_kernel(const float* __restrict__ l1w, const float* __restrict__ l1b,
                     const float* __restrict__ l2w, const float* __restrict__ l2b,
                     float* __restrict__ out)
{
    __shared__ float pooled[256];
    __shared__ float z[128];
    const int g = blockIdx.x, t = threadIdx.x;
    const int s = g_starts[g], e = g_starts[g + 1];
    float sum = 0.f;
    for (int r = s; r < e; r++) sum += g_h2[(size_t)r * 256 + t];
    float inv = 1.0f / (float)max(e - s, 1);
    pooled[t] = sum * inv;
    __syncthreads();
    if (t < 128) {
        float a = l1b[t];
        for (int o = 0; o < 256; o++) a = fmaf(pooled[o], l1w[o * 128 + t], a);
        z[t] = fmaxf(a, 0.f);
    }
    __syncthreads();
    if (t == 0) {
        float a = l2b[0];
        for (int j = 0; j < 128; j++) a = fmaf(z[j], l2w[j], a);
        out[g] = 1.0f / (1.0f + expf(-a));
    }
}

// ---------------- launch ----------------
extern "C" void kernel_launch(void* const* d_in, const int* in_sizes, int n_in,
                              void* d_out, int out_size)
{
    const float* x       = (const float*)d_in[0];
    const int*   ei      = (const int*)d_in[1];
    const float* ea      = (const float*)d_in[2];
    const int*   batch   = (const int*)d_in[3];
    const float* nn1_w   = (const float*)d_in[4];
    const float* nn1_b   = (const float*)d_in[5];
    const float* root1_w = (const float*)d_in[6];
    const float* bias1   = (const float*)d_in[7];
    const float* nn2_w   = (const float*)d_in[8];
    const float* nn2_b   = (const float*)d_in[9];
    const float* root2_w = (const float*)d_in[10];
    const float* bias2   = (const float*)d_in[11];
    const float* l1w     = (const float*)d_in[12];
    const float* l1b     = (const float*)d_in[13];
    const float* l2w     = (const float*)d_in[14];
    const float* l2b     = (const float*)d_in[15];
    const int* srcA = ei;
    const int* dstA = ei + NE;
    float* out = (float*)d_out;

    void *pPh, *pPl, *pW1, *pW2, *ph, *ph2;
    cudaGetSymbolAddress(&pPh, g_Ph);
    cudaGetSymbolAddress(&pPl, g_Pl);
    cudaGetSymbolAddress(&pW1, g_Wt1);
    cudaGetSymbolAddress(&pW2, g_Wt2);
    cudaGetSymbolAddress(&ph, g_h);
    cudaGetSymbolAddress(&ph2, g_h2);

    cudaFuncSetAttribute(gemm_mma<2176, true>,  cudaFuncAttributeMaxDynamicSharedMemorySize, GEMM_SMEM);
    cudaFuncSetAttribute(gemm_mma<8704, false>, cudaFuncAttributeMaxDynamicSharedMemorySize, GEMM_SMEM);

    zero_deg_kernel<<<16, 256>>>();
    rank_kernel<<<32, 256>>>(dstA);
    scan_kernel<<<1, 1024>>>();
    place_kernel<<<32, 256>>>(dstA);
    starts_kernel<<<1, 512>>>(batch);
    prep_kernel<<<dim3(272, 8, 2), 256>>>(nn1_w, nn1_b, root1_w, nn2_w, nn2_b, root2_w);

    // conv1
    scatter_kernel<6><<<NN, 256>>>(x, ea, srcA);
    gemm_mma<2176, true><<<dim3(32, 4), 256, GEMM_SMEM>>>(
        (const __half*)pPh, (const __half*)pPl, (const __half*)pW1, bias1, (float*)ph);
    // conv2
    scatter_kernel<8><<<NN, 256>>>((const float*)ph, ea, srcA);
    gemm_mma<8704, false><<<dim3(32, 4), 256, GEMM_SMEM>>>(
        (const __half*)pPh, (const __half*)pPl, (const __half*)pW2, bias2, (float*)ph2);

    pool_mlp_kernel<<<NG, 256>>>(l1w, l1b, l2w, l2b, out);
}